// round 2
// baseline (speedup 1.0000x reference)
#include <cuda_runtime.h>
#include <stdint.h>

#define NUM_USERS 100000
#define NUM_ITEMS 50000
#define EMB       64
#define CHUNKS    16   // EMB/4 float4 chunks per node row

// ---------------- scratch (static device globals; no allocs allowed) --------
__device__ float g_acc_u[(size_t)NUM_USERS * EMB];   // 25.6 MB
__device__ float g_acc_i[(size_t)NUM_ITEMS * EMB];   // 12.8 MB
__device__ float g_invdeg_u[NUM_USERS];
__device__ float g_invdeg_i[NUM_ITEMS];
__device__ int   g_deg_u[NUM_USERS];
__device__ int   g_deg_i[NUM_ITEMS];

// ---------------- helpers ----------------------------------------------------
__device__ __forceinline__ void red_add_v4(float* addr, float4 v) {
    // sm_90+ vectorized reduction: one 16B atomic instead of 4 scalar atomics
    asm volatile("red.global.add.v4.f32 [%0], {%1, %2, %3, %4};"
                 :: "l"(addr), "f"(v.x), "f"(v.y), "f"(v.z), "f"(v.w)
                 : "memory");
}

// ---------------- kernels -----------------------------------------------------

// Zero accumulators + degree counters (runs once per graph replay).
__global__ void k_zero() {
    const size_t nU = (size_t)NUM_USERS * EMB;
    const size_t nI = (size_t)NUM_ITEMS * EMB;
    size_t stride = (size_t)gridDim.x * blockDim.x;
    for (size_t idx = (size_t)blockIdx.x * blockDim.x + threadIdx.x;
         idx < nU; idx += stride) g_acc_u[idx] = 0.0f;
    for (size_t idx = (size_t)blockIdx.x * blockDim.x + threadIdx.x;
         idx < nI; idx += stride) g_acc_i[idx] = 0.0f;
    for (size_t idx = (size_t)blockIdx.x * blockDim.x + threadIdx.x;
         idx < NUM_USERS; idx += stride) g_deg_u[idx] = 0;
    for (size_t idx = (size_t)blockIdx.x * blockDim.x + threadIdx.x;
         idx < NUM_ITEMS; idx += stride) g_deg_i[idx] = 0;
}

// Count degrees per direction.
__global__ void k_degree(const int* __restrict__ src,
                         const int* __restrict__ dst, int ne) {
    int stride = gridDim.x * blockDim.x;
    for (int e = blockIdx.x * blockDim.x + threadIdx.x; e < ne; e += stride) {
        atomicAdd(&g_deg_u[__ldg(src + e)], 1);
        atomicAdd(&g_deg_i[__ldg(dst + e)], 1);
    }
}

// inv_deg = deg > 0 ? 1/deg : 0   (users then items, one flat index space)
__global__ void k_invdeg() {
    int idx = blockIdx.x * blockDim.x + threadIdx.x;
    if (idx < NUM_USERS) {
        int d = g_deg_u[idx];
        g_invdeg_u[idx] = (d > 0) ? (1.0f / (float)d) : 0.0f;
    } else if (idx < NUM_USERS + NUM_ITEMS) {
        int j = idx - NUM_USERS;
        int d = g_deg_i[j];
        g_invdeg_i[j] = (d > 0) ? (1.0f / (float)d) : 0.0f;
    }
}

// Edge scatter: both directions fused. 16 threads per edge, one float4 each.
// Reads u[src] row -> red into acc_i[dst]; reads i[dst] row -> red into acc_u[src].
__global__ void k_scatter(const float* __restrict__ ufeat,
                          const float* __restrict__ ifeat,
                          const int* __restrict__ src,
                          const int* __restrict__ dst, int ne) {
    int tid = blockIdx.x * blockDim.x + threadIdx.x;
    int e = tid >> 4;
    int c = tid & 15;
    if (e >= ne) return;
    int su = __ldg(src + e);
    int di = __ldg(dst + e);

    size_t uoff = (size_t)su * EMB + (size_t)c * 4;
    size_t ioff = (size_t)di * EMB + (size_t)c * 4;

    float4 a = __ldg((const float4*)(ufeat + uoff));   // u[src] chunk
    float4 b = __ldg((const float4*)(ifeat + ioff));   // i[dst] chunk

    red_add_v4(&g_acc_i[ioff], a);   // user -> item aggregation
    red_add_v4(&g_acc_u[uoff], b);   // item -> user aggregation
}

// Combine: out = acc * inv_deg + emb_in * sw ; also re-zero acc for next round.
__global__ void k_combine(const float* __restrict__ emb_in,
                          const float* __restrict__ sw,
                          float* __restrict__ acc,
                          const float* __restrict__ invdeg,
                          float* __restrict__ out, int nnodes) {
    int tid = blockIdx.x * blockDim.x + threadIdx.x;
    int node = tid >> 4;
    int c = tid & 15;
    if (node >= nnodes) return;
    size_t off = (size_t)node * EMB + (size_t)c * 4;

    float4 a = *(const float4*)(acc + off);
    float4 e = __ldg((const float4*)(emb_in + off));
    float inv = __ldg(invdeg + node);
    float s   = __ldg(sw + node);

    float4 r;
    r.x = fmaf(a.x, inv, e.x * s);
    r.y = fmaf(a.y, inv, e.y * s);
    r.z = fmaf(a.z, inv, e.z * s);
    r.w = fmaf(a.w, inv, e.w * s);

    *(float4*)(out + off) = r;
    *(float4*)(acc + off) = make_float4(0.f, 0.f, 0.f, 0.f);
}

// ---------------- launch ------------------------------------------------------
extern "C" void kernel_launch(void* const* d_in, const int* in_sizes, int n_in,
                              void* d_out, int out_size) {
    const float* user_emb = (const float*)d_in[0];   // [100000, 64]
    const float* item_emb = (const float*)d_in[1];   // [50000, 64]
    const float* u_sw     = (const float*)d_in[2];   // [100000, 1]
    const float* i_sw     = (const float*)d_in[3];   // [50000, 1]
    const int*   e_src    = (const int*)d_in[4];     // [NE]
    const int*   e_dst    = (const int*)d_in[5];     // [NE]
    const int    ne       = in_sizes[4];

    float* out_u = (float*)d_out;                           // [100000, 64]
    float* out_i = (float*)d_out + (size_t)NUM_USERS * EMB; // [50000, 64]

    // resolve device-symbol addresses (host-side query, capture-safe)
    float *acc_u, *acc_i, *invd_u, *invd_i;
    cudaGetSymbolAddress((void**)&acc_u, g_acc_u);
    cudaGetSymbolAddress((void**)&acc_i, g_acc_i);
    cudaGetSymbolAddress((void**)&invd_u, g_invdeg_u);
    cudaGetSymbolAddress((void**)&invd_i, g_invdeg_i);

    const int TPB = 256;

    // 0) zero scratch (needed every replay) + degrees + inv_deg
    k_zero<<<2048, TPB>>>();
    k_degree<<<(ne + TPB - 1) / TPB, TPB>>>(e_src, e_dst, ne);
    k_invdeg<<<(NUM_USERS + NUM_ITEMS + TPB - 1) / TPB, TPB>>>();

    long long nsc = (long long)ne * CHUNKS;
    int scatter_blocks = (int)((nsc + TPB - 1) / TPB);
    int cu_blocks = (int)(((long long)NUM_USERS * CHUNKS + TPB - 1) / TPB);
    int ci_blocks = (int)(((long long)NUM_ITEMS * CHUNKS + TPB - 1) / TPB);

    // ---- round 1 ----
    k_scatter<<<scatter_blocks, TPB>>>(user_emb, item_emb, e_src, e_dst, ne);
    k_combine<<<cu_blocks, TPB>>>(user_emb, u_sw, acc_u, invd_u, out_u, NUM_USERS);
    k_combine<<<ci_blocks, TPB>>>(item_emb, i_sw, acc_i, invd_i, out_i, NUM_ITEMS);

    // ---- round 2 (acc re-zeroed by round-1 combines) ----
    k_scatter<<<scatter_blocks, TPB>>>(out_u, out_i, e_src, e_dst, ne);
    k_combine<<<cu_blocks, TPB>>>(out_u, u_sw, acc_u, invd_u, out_u, NUM_USERS);
    k_combine<<<ci_blocks, TPB>>>(out_i, i_sw, acc_i, invd_i, out_i, NUM_ITEMS);
}